// round 5
// baseline (speedup 1.0000x reference)
#include <cuda_runtime.h>
#include <cuda_bf16.h>
#include <cstdint>
#include <math.h>

// ---------------------------------------------------------------------------
// Problem constants
// ---------------------------------------------------------------------------
#define BATCH 8
#define SEQ   2048
#define EMBED 1024
#define BS    (BATCH * SEQ)          // 16384

// ---------------------------------------------------------------------------
// Device-global scratch (allocation-free rule)
// ---------------------------------------------------------------------------
__device__ __nv_bfloat16 g_xh[(size_t)BS * EMBED];
__device__ __nv_bfloat16 g_xl[(size_t)BS * EMBED];
__device__ __nv_bfloat16 g_Wqh[EMBED * EMBED], g_Wql[EMBED * EMBED];
__device__ __nv_bfloat16 g_Wkh[EMBED * EMBED], g_Wkl[EMBED * EMBED];
__device__ __nv_bfloat16 g_Wvh[EMBED * EMBED], g_Wvl[EMBED * EMBED];
__device__ __nv_bfloat16 g_Qh[(size_t)BS * EMBED], g_Ql[(size_t)BS * EMBED];
__device__ __nv_bfloat16 g_Kh[(size_t)BS * EMBED], g_Kl[(size_t)BS * EMBED];
// V stored pre-transposed: [EMBED rows][BS cols] (per-batch window of 2048 cols)
__device__ __nv_bfloat16 g_Vth[(size_t)EMBED * BS], g_Vtl[(size_t)EMBED * BS];
__device__ float         g_S[(size_t)BATCH * SEQ * SEQ];
__device__ __nv_bfloat16 g_Ph[(size_t)BATCH * SEQ * SEQ], g_Pl[(size_t)BATCH * SEQ * SEQ];

// ---------------------------------------------------------------------------
// Helpers
// ---------------------------------------------------------------------------
__device__ __forceinline__ uint32_t smem_u32(const void* p) {
    uint32_t a;
    asm("{ .reg .u64 t; cvta.to.shared.u64 t, %1; cvt.u32.u64 %0, t; }" : "=r"(a) : "l"(p));
    return a;
}

#define CP_ASYNC16(sm, gp) \
    asm volatile("cp.async.cg.shared.global [%0], [%1], 16;" :: "r"(sm), "l"(gp) : "memory")
#define CP_COMMIT()  asm volatile("cp.async.commit_group;" ::: "memory")
#define CP_WAIT0()   asm volatile("cp.async.wait_group 0;" ::: "memory")
#define CP_WAIT1()   asm volatile("cp.async.wait_group 1;" ::: "memory")

__device__ __forceinline__ void ldsm_x4(uint32_t* r, uint32_t addr) {
    asm volatile("ldmatrix.sync.aligned.m8n8.x4.shared.b16 {%0,%1,%2,%3}, [%4];"
                 : "=r"(r[0]), "=r"(r[1]), "=r"(r[2]), "=r"(r[3]) : "r"(addr));
}

__device__ __forceinline__ void mma16816(float* c, const uint32_t* a, const uint32_t* b) {
    asm volatile(
        "mma.sync.aligned.m16n8k16.row.col.f32.bf16.bf16.f32 "
        "{%0,%1,%2,%3}, {%4,%5,%6,%7}, {%8,%9}, {%0,%1,%2,%3};"
        : "+f"(c[0]), "+f"(c[1]), "+f"(c[2]), "+f"(c[3])
        : "r"(a[0]), "r"(a[1]), "r"(a[2]), "r"(a[3]), "r"(b[0]), "r"(b[1]));
}

// byte offset of 16B chunk (row, c) inside a [rows][64 bf16] tile, xor-swizzled
__device__ __forceinline__ uint32_t swz(int row, int c) {
    return (uint32_t)((row * 8 + (c ^ (row & 7))) * 16);
}

// ---------------------------------------------------------------------------
// HMMA GEMM NT: C[M,N] = A[M,K] * B[N,K]^T, two-term bf16 split operands
//   D += AhBh + AhBl + AlBh (fp32 accum in registers)
// CTA tile 128x256, warp tile 64x64 (8 warps, 2x4), K-chunk 64,
// double-buffered cp.async SMEM pipeline (96KB/stage).
// Mainloop is TERM-MAJOR: three passes over the 32 acc tiles per k-step so
// same-accumulator MMAs are ~32 instructions apart (RAW latency hidden).
// MODE 0: C = fp32 -> Cf
// MODE 1: v = (acc + bias[col]) * scale; split -> Ch/Cl. blockIdx.z selects
//         operand-set {Bh,Bl,bias,scale,Ch,Cl} (z=0) or the "2" set (z=1).
// MODE 2: v = (acc + bias[row]) * scale; split -> Ch/Cl (bf16)
// ---------------------------------------------------------------------------
#define STAGE_BYTES 98304
#define A_H_OFF 0
#define A_L_OFF 16384
#define B_H_OFF 32768
#define B_L_OFF 65536
#define GEMM_SMEM (2 * STAGE_BYTES)

template <int MODE>
__global__ void __launch_bounds__(256, 1)
gemm_tc(const __nv_bfloat16* __restrict__ Ah, const __nv_bfloat16* __restrict__ Al,
        const __nv_bfloat16* Bh, const __nv_bfloat16* Bl,
        const float* bias, float scale,
        float* __restrict__ Cf, __nv_bfloat16* Ch, __nv_bfloat16* Cl,
        int lda, int ldb, int ldc, int nchunk,
        long long strideA, long long strideB, long long strideC,
        const __nv_bfloat16* Bh2, const __nv_bfloat16* Bl2,
        const float* bias2, float scale2,
        __nv_bfloat16* Ch2, __nv_bfloat16* Cl2)
{
    extern __shared__ char smem[];
    const uint32_t sbase = smem_u32(smem);
    const int tid = threadIdx.x;
    const int wid = tid >> 5;
    const int lane = tid & 31;
    const int wm = wid & 1;          // 0..1  M direction (64 rows each)
    const int wn = wid >> 1;         // 0..3  N direction (64 cols each)

    const long long z = blockIdx.z;
    if (MODE == 1) {
        if (z == 1) {
            Bh = Bh2; Bl = Bl2; bias = bias2; scale = scale2; Ch = Ch2; Cl = Cl2;
        }
    } else {
        Ah += z * strideA;  Al += z * strideA;
        Bh += z * strideB;  Bl += z * strideB;
    }

    const int rowA0 = blockIdx.y * 128;
    const int colB0 = blockIdx.x * 256;

    float acc[4][8][4];
#pragma unroll
    for (int mt = 0; mt < 4; mt++)
#pragma unroll
        for (int nt = 0; nt < 8; nt++)
#pragma unroll
            for (int r = 0; r < 4; r++) acc[mt][nt][r] = 0.f;

    const __nv_bfloat16* gAh = Ah + (size_t)rowA0 * lda;
    const __nv_bfloat16* gAl = Al + (size_t)rowA0 * lda;
    const __nv_bfloat16* gBh = Bh + (size_t)colB0 * ldb;
    const __nv_bfloat16* gBl = Bl + (size_t)colB0 * ldb;

    // issue all cp.async for one stage: A 128x64 (h+l), B 256x64 (h+l)
    auto issue_stage = [&](int kc, int stg) {
        const uint32_t sb = sbase + stg * STAGE_BYTES;
        const int k0 = kc * 64;
#pragma unroll
        for (int it = 0; it < 4; it++) {
            int idx = it * 256 + tid;
            int r = idx >> 3, c = idx & 7;
            uint32_t so = swz(r, c);
            CP_ASYNC16(sb + A_H_OFF + so, gAh + (size_t)r * lda + k0 + c * 8);
            CP_ASYNC16(sb + A_L_OFF + so, gAl + (size_t)r * lda + k0 + c * 8);
        }
#pragma unroll
        for (int it = 0; it < 8; it++) {
            int idx = it * 256 + tid;
            int r = idx >> 3, c = idx & 7;
            uint32_t so = swz(r, c);
            CP_ASYNC16(sb + B_H_OFF + so, gBh + (size_t)r * ldb + k0 + c * 8);
            CP_ASYNC16(sb + B_L_OFF + so, gBl + (size_t)r * ldb + k0 + c * 8);
        }
    };

    issue_stage(0, 0);
    CP_COMMIT();

    // ldmatrix lane address components
    const int a_row = lane & 15;                         // row within 16-row m-tile
    const int a_csel = lane >> 4;                        // 0/1 -> 8-col halves
    const int b_row = (lane & 7) + ((lane >> 4) << 3);   // row within 16-row n-tile
    const int b_csel = (lane >> 3) & 1;

    for (int kc = 0; kc < nchunk; kc++) {
        const int stg = kc & 1;
        if (kc + 1 < nchunk) {
            issue_stage(kc + 1, stg ^ 1);
            CP_COMMIT();
            CP_WAIT1();
        } else {
            CP_WAIT0();
        }
        __syncthreads();

        const uint32_t sb = sbase + stg * STAGE_BYTES;
        const uint32_t aH = sb + A_H_OFF, aL = sb + A_L_OFF;
        const uint32_t bH = sb + B_H_OFF, bL = sb + B_L_OFF;

#pragma unroll
        for (int ks = 0; ks < 4; ks++) {
            uint32_t fAh[4][4], fAl[4][4], fBh[4][4], fBl[4][4];
            const int kchunk = ks * 2;

            // hi fragments first
#pragma unroll
            for (int mt = 0; mt < 4; mt++)
                ldsm_x4(fAh[mt], aH + swz(wm * 64 + mt * 16 + a_row, kchunk + a_csel));
#pragma unroll
            for (int g = 0; g < 4; g++)
                ldsm_x4(fBh[g], bH + swz(wn * 64 + g * 16 + b_row, kchunk + b_csel));

            // pass 1: Ah * Bh over all 32 tiles (independent accumulators)
#pragma unroll
            for (int mt = 0; mt < 4; mt++)
#pragma unroll
                for (int nt = 0; nt < 8; nt++)
                    mma16816(acc[mt][nt], fAh[mt], &fBh[nt >> 1][(nt & 1) * 2]);

            // lo fragments load overlaps pass-1 tensor work
#pragma unroll
            for (int g = 0; g < 4; g++)
                ldsm_x4(fBl[g], bL + swz(wn * 64 + g * 16 + b_row, kchunk + b_csel));
#pragma unroll
            for (int mt = 0; mt < 4; mt++)
                ldsm_x4(fAl[mt], aL + swz(wm * 64 + mt * 16 + a_row, kchunk + a_csel));

            // pass 2: Ah * Bl
#pragma unroll
            for (int mt = 0; mt < 4; mt++)
#pragma unroll
                for (int nt = 0; nt < 8; nt++)
                    mma16816(acc[mt][nt], fAh[mt], &fBl[nt >> 1][(nt & 1) * 2]);

            // pass 3: Al * Bh
#pragma unroll
            for (int mt = 0; mt < 4; mt++)
#pragma unroll
                for (int nt = 0; nt < 8; nt++)
                    mma16816(acc[mt][nt], fAl[mt], &fBh[nt >> 1][(nt & 1) * 2]);
        }
        __syncthreads();
    }

    // ------------------------------ epilogue ------------------------------
    const int lrow = (lane >> 2);        // 0..7
    const int lcol = (lane & 3) * 2;     // 0,2,4,6

#pragma unroll
    for (int mt = 0; mt < 4; mt++) {
#pragma unroll
        for (int half = 0; half < 2; half++) {
            const int row = rowA0 + wm * 64 + mt * 16 + lrow + half * 8;
            float rb = (MODE == 2) ? bias[row] : 0.f;
#pragma unroll
            for (int nt = 0; nt < 8; nt++) {
                const int col = colB0 + wn * 64 + nt * 8 + lcol;
                float v0 = acc[mt][nt][half * 2 + 0];
                float v1 = acc[mt][nt][half * 2 + 1];
                if (MODE == 0) {
                    float2 o = make_float2(v0, v1);
                    *(float2*)(Cf + z * strideC + (size_t)row * ldc + col) = o;
                } else {
                    if (MODE == 1) { v0 = (v0 + bias[col]) * scale; v1 = (v1 + bias[col + 1]) * scale; }
                    else           { v0 = (v0 + rb) * scale;       v1 = (v1 + rb) * scale; }
                    __nv_bfloat16 h0 = __float2bfloat16(v0);
                    __nv_bfloat16 h1 = __float2bfloat16(v1);
                    __nv_bfloat16 l0 = __float2bfloat16(v0 - __bfloat162float(h0));
                    __nv_bfloat16 l1 = __float2bfloat16(v1 - __bfloat162float(h1));
                    uint32_t hw = (uint32_t)__bfloat16_as_ushort(h0) |
                                  ((uint32_t)__bfloat16_as_ushort(h1) << 16);
                    uint32_t lw = (uint32_t)__bfloat16_as_ushort(l0) |
                                  ((uint32_t)__bfloat16_as_ushort(l1) << 16);
                    *(uint32_t*)(Ch + (size_t)row * ldc + col) = hw;
                    *(uint32_t*)(Cl + (size_t)row * ldc + col) = lw;
                }
            }
        }
    }
}

// ---------------------------------------------------------------------------
// fp32 -> (bf16 hi, bf16 lo) split
// ---------------------------------------------------------------------------
__global__ void __launch_bounds__(256, 8)
split_kernel(const float* __restrict__ in, __nv_bfloat16* __restrict__ hi,
             __nv_bfloat16* __restrict__ lo, size_t n)
{
    size_t i = ((size_t)blockIdx.x * blockDim.x + threadIdx.x) * 8;
    if (i >= n) return;
    float4 a = *(const float4*)(in + i);
    float4 b = *(const float4*)(in + i + 4);
    float v[8] = {a.x, a.y, a.z, a.w, b.x, b.y, b.z, b.w};
    alignas(16) uint32_t hw[4], lw[4];
#pragma unroll
    for (int c = 0; c < 8; c += 2) {
        __nv_bfloat16 h0 = __float2bfloat16(v[c]);
        __nv_bfloat16 h1 = __float2bfloat16(v[c + 1]);
        __nv_bfloat16 l0 = __float2bfloat16(v[c] - __bfloat162float(h0));
        __nv_bfloat16 l1 = __float2bfloat16(v[c + 1] - __bfloat162float(h1));
        hw[c >> 1] = (uint32_t)__bfloat16_as_ushort(h0) | ((uint32_t)__bfloat16_as_ushort(h1) << 16);
        lw[c >> 1] = (uint32_t)__bfloat16_as_ushort(l0) | ((uint32_t)__bfloat16_as_ushort(l1) << 16);
    }
    *(uint4*)(hi + i) = *(const uint4*)(&hw[0]);
    *(uint4*)(lo + i) = *(const uint4*)(&lw[0]);
}

// ---------------------------------------------------------------------------
// Row softmax (fp32 in) -> split bf16 out. One block per row of SEQ floats.
// ---------------------------------------------------------------------------
__global__ void __launch_bounds__(256, 4)
softmax_split(const float* __restrict__ Sm, __nv_bfloat16* __restrict__ Ph,
              __nv_bfloat16* __restrict__ Pl)
{
    const float* row = Sm + (size_t)blockIdx.x * SEQ;
    const int t = threadIdx.x;

    float v[8];
    *(float4*)(v + 0) = *(const float4*)(row + t * 8 + 0);
    *(float4*)(v + 4) = *(const float4*)(row + t * 8 + 4);

    float mx = v[0];
#pragma unroll
    for (int i = 1; i < 8; i++) mx = fmaxf(mx, v[i]);

    __shared__ float red[256];
    red[t] = mx;
    __syncthreads();
#pragma unroll
    for (int s = 128; s > 0; s >>= 1) {
        if (t < s) red[t] = fmaxf(red[t], red[t + s]);
        __syncthreads();
    }
    mx = red[0];
    __syncthreads();

    float sum = 0.f;
#pragma unroll
    for (int i = 0; i < 8; i++) {
        v[i] = __expf(v[i] - mx);
        sum += v[i];
    }
    red[t] = sum;
    __syncthreads();
#pragma unroll
    for (int s = 128; s > 0; s >>= 1) {
        if (t < s) red[t] += red[t + s];
        __syncthreads();
    }
    const float inv = 1.f / red[0];

    alignas(16) uint32_t hw[4], lw[4];
#pragma unroll
    for (int c = 0; c < 8; c += 2) {
        float v0 = v[c] * inv, v1 = v[c + 1] * inv;
        __nv_bfloat16 h0 = __float2bfloat16(v0);
        __nv_bfloat16 h1 = __float2bfloat16(v1);
        __nv_bfloat16 l0 = __float2bfloat16(v0 - __bfloat162float(h0));
        __nv_bfloat16 l1 = __float2bfloat16(v1 - __bfloat162float(h1));
        hw[c >> 1] = (uint32_t)__bfloat16_as_ushort(h0) | ((uint32_t)__bfloat16_as_ushort(h1) << 16);
        lw[c >> 1] = (uint32_t)__bfloat16_as_ushort(l0) | ((uint32_t)__bfloat16_as_ushort(l1) << 16);
    }
    size_t base = (size_t)blockIdx.x * SEQ + t * 8;
    *(uint4*)(Ph + base) = *(const uint4*)(&hw[0]);
    *(uint4*)(Pl + base) = *(const uint4*)(&lw[0]);
}

// ---------------------------------------------------------------------------
// Launch
// ---------------------------------------------------------------------------
extern "C" void kernel_launch(void* const* d_in, const int* in_sizes, int n_in,
                              void* d_out, int out_size)
{
    const float* x  = (const float*)d_in[0];
    const float* Wq = (const float*)d_in[1];
    const float* bq = (const float*)d_in[2];
    const float* Wk = (const float*)d_in[3];
    const float* bk = (const float*)d_in[4];
    const float* Wv = (const float*)d_in[5];
    const float* bv = (const float*)d_in[6];
    float* out = (float*)d_out;

    cudaFuncSetAttribute((const void*)gemm_tc<0>, cudaFuncAttributeMaxDynamicSharedMemorySize, GEMM_SMEM);
    cudaFuncSetAttribute((const void*)gemm_tc<1>, cudaFuncAttributeMaxDynamicSharedMemorySize, GEMM_SMEM);
    cudaFuncSetAttribute((const void*)gemm_tc<2>, cudaFuncAttributeMaxDynamicSharedMemorySize, GEMM_SMEM);

    __nv_bfloat16 *xh, *xl, *Wqh, *Wql, *Wkh, *Wkl, *Wvh, *Wvl;
    __nv_bfloat16 *Qh, *Ql, *Kh, *Kl, *Vth, *Vtl, *Ph, *Pl;
    float* Sp;
    cudaGetSymbolAddress((void**)&xh, g_xh);   cudaGetSymbolAddress((void**)&xl, g_xl);
    cudaGetSymbolAddress((void**)&Wqh, g_Wqh); cudaGetSymbolAddress((void**)&Wql, g_Wql);
    cudaGetSymbolAddress((void**)&Wkh, g_Wkh); cudaGetSymbolAddress((void**)&Wkl, g_Wkl);
    cudaGetSymbolAddress((void**)&Wvh, g_Wvh); cudaGetSymbolAddress((void**)&Wvl, g_Wvl);
    cudaGetSymbolAddress((void**)&Qh, g_Qh);   cudaGetSymbolAddress((void**)&Ql, g_Ql);
    cudaGetSymbolAddress((void**)&Kh, g_Kh);   cudaGetSymbolAddress((void**)&Kl, g_Kl);
    cudaGetSymbolAddress((void**)&Vth, g_Vth); cudaGetSymbolAddress((void**)&Vtl, g_Vtl);
    cudaGetSymbolAddress((void**)&Ph, g_Ph);   cudaGetSymbolAddress((void**)&Pl, g_Pl);
    cudaGetSymbolAddress((void**)&Sp, g_S);

    const float qscale = 0.03125f;   // 1/sqrt(1024), exact power of two

    // 1) split inputs to bf16 hi/lo
    split_kernel<<<(size_t)BS * EMBED / 2048, 256>>>(x,  xh,  xl,  (size_t)BS * EMBED);
    split_kernel<<<EMBED * EMBED / 2048, 256>>>(Wq, Wqh, Wql, (size_t)EMBED * EMBED);
    split_kernel<<<EMBED * EMBED / 2048, 256>>>(Wk, Wkh, Wkl, (size_t)EMBED * EMBED);
    split_kernel<<<EMBED * EMBED / 2048, 256>>>(Wv, Wvh, Wvl, (size_t)EMBED * EMBED);

    // 2) Q = (x Wq^T + bq) * qscale  (z=0) ;  K = x Wk^T + bk  (z=1)
    {
        dim3 grid(EMBED / 256, BS / 128, 2);   // (4, 128, 2)
        gemm_tc<1><<<grid, 256, GEMM_SMEM>>>(xh, xl, Wqh, Wql, bq, qscale,
                                             nullptr, Qh, Ql,
                                             EMBED, EMBED, EMBED, EMBED / 64, 0, 0, 0,
                                             Wkh, Wkl, bk, 1.0f, Kh, Kl);
    }
    // 3) Vt[e, bs] = Wv x^T + bv  (row bias), ldc = BS
    {
        dim3 grid(BS / 256, EMBED / 128, 1);   // (64, 8)
        gemm_tc<2><<<grid, 256, GEMM_SMEM>>>(Wvh, Wvl, xh, xl, bv, 1.0f,
                                             nullptr, Vth, Vtl,
                                             EMBED, EMBED, BS, EMBED / 64, 0, 0, 0,
                                             nullptr, nullptr, nullptr, 0.f, nullptr, nullptr);
    }
    // 4) scores = Q K^T (scale already folded into Q), batched, fp32 out
    {
        dim3 grid(SEQ / 256, SEQ / 128, BATCH);   // (8, 16, 8)
        gemm_tc<0><<<grid, 256, GEMM_SMEM>>>(Qh, Ql, Kh, Kl, nullptr, 1.0f,
                                             Sp, nullptr, nullptr,
                                             EMBED, EMBED, SEQ, EMBED / 64,
                                             (long long)SEQ * EMBED,
                                             (long long)SEQ * EMBED,
                                             (long long)SEQ * SEQ,
                                             nullptr, nullptr, nullptr, 0.f, nullptr, nullptr);
    }
    // 5) softmax -> split bf16 P
    softmax_split<<<BATCH * SEQ, 256>>>(Sp, Ph, Pl);

    // 6) out = P V  (B = Vt rows, per-batch column window), fp32 out
    {
        dim3 grid(EMBED / 256, SEQ / 128, BATCH);   // (4, 16, 8)
        gemm_tc<0><<<grid, 256, GEMM_SMEM>>>(Ph, Pl, Vth, Vtl, nullptr, 1.0f,
                                             out, nullptr, nullptr,
                                             SEQ, BS, EMBED, SEQ / 64,
                                             (long long)SEQ * SEQ,
                                             (long long)SEQ,
                                             (long long)SEQ * EMBED,
                                             nullptr, nullptr, nullptr, 0.f, nullptr, nullptr);
    }
}

// round 7
// speedup vs baseline: 1.4992x; 1.4992x over previous
#include <cuda_runtime.h>
#include <cuda_fp16.h>
#include <cstdint>
#include <math.h>

#define BATCH 8
#define SEQ   2048
#define EMBED 1024
#define BS    (BATCH * SEQ)          // 16384

// ---------------------------------------------------------------------------
// Device-global scratch (allocation-free rule)
// ---------------------------------------------------------------------------
__device__ __half g_xh[(size_t)BS * EMBED];
__device__ __half g_xl[(size_t)BS * EMBED];
__device__ __half g_Wq[EMBED * EMBED];
__device__ __half g_Wk[EMBED * EMBED];
__device__ __half g_Wv[EMBED * EMBED];
__device__ __half g_Qh[(size_t)BS * EMBED], g_Ql[(size_t)BS * EMBED];
__device__ __half g_Kh[(size_t)BS * EMBED];
__device__ __half g_Vth[(size_t)EMBED * BS];   // V pre-transposed [EMBED][BS]
__device__ float  g_S[(size_t)BATCH * SEQ * SEQ];
__device__ __half g_Ph[(size_t)BATCH * SEQ * SEQ], g_Pl[(size_t)BATCH * SEQ * SEQ];

// ---------------------------------------------------------------------------
// Helpers
// ---------------------------------------------------------------------------
__device__ __forceinline__ uint32_t smem_u32(const void* p) {
    uint32_t a;
    asm("{ .reg .u64 t; cvta.to.shared.u64 t, %1; cvt.u32.u64 %0, t; }" : "=r"(a) : "l"(p));
    return a;
}

#define CP_ASYNC16(sm, gp) \
    asm volatile("cp.async.cg.shared.global [%0], [%1], 16;" :: "r"(sm), "l"(gp) : "memory")
#define CP_COMMIT()  asm volatile("cp.async.commit_group;" ::: "memory")
#define CP_WAIT0()   asm volatile("cp.async.wait_group 0;" ::: "memory")
#define CP_WAIT1()   asm volatile("cp.async.wait_group 1;" ::: "memory")
#define CP_WAIT2()   asm volatile("cp.async.wait_group 2;" ::: "memory")

__device__ __forceinline__ void ldsm_x4(uint32_t* r, uint32_t addr) {
    asm volatile("ldmatrix.sync.aligned.m8n8.x4.shared.b16 {%0,%1,%2,%3}, [%4];"
                 : "=r"(r[0]), "=r"(r[1]), "=r"(r[2]), "=r"(r[3]) : "r"(addr));
}

__device__ __forceinline__ void mma16816(float* c, const uint32_t* a, const uint32_t* b) {
    asm volatile(
        "mma.sync.aligned.m16n8k16.row.col.f32.f16.f16.f32 "
        "{%0,%1,%2,%3}, {%4,%5,%6,%7}, {%8,%9}, {%0,%1,%2,%3};"
        : "+f"(c[0]), "+f"(c[1]), "+f"(c[2]), "+f"(c[3])
        : "r"(a[0]), "r"(a[1]), "r"(a[2]), "r"(a[3]), "r"(b[0]), "r"(b[1]));
}

// byte offset of 16B chunk (row, c) inside a [rows][64 fp16] tile, xor-swizzled
__device__ __forceinline__ uint32_t swz(int row, int c) {
    return (uint32_t)((row * 8 + (c ^ (row & 7))) * 16);
}

__device__ __forceinline__ uint32_t pack_half2(float v0, float v1) {
    __half h0 = __float2half(v0), h1 = __float2half(v1);
    return (uint32_t)__half_as_ushort(h0) | ((uint32_t)__half_as_ushort(h1) << 16);
}

// ---------------------------------------------------------------------------
// HMMA GEMM NT: C[M,N] = (Ah[+Al])[M,K] * B[N,K]^T, fp16 in, fp32 accum.
// CTA tile 128x256, warp tile 64x64 (8 warps, 2x4), K-chunk 64,
// 3-stage cp.async pipeline (64KB/stage).
// MODE 0: two-term A (Ah+Al); C -> fp32 Cf
// MODE 1: two-term A; v=(acc+bias[col])*scale -> Ch (+Cl if non-null);
//         blockIdx.z picks {B,bias,scale,Ch,Cl} (z=0) or the "2" set (z=1)
// MODE 2: SINGLE-term A (Al ignored); v=acc+bias[row] -> Ch only
// ---------------------------------------------------------------------------
#define STAGE_BYTES 65536
#define A_H_OFF 0
#define A_L_OFF 16384
#define B_OFF   32768
#define GEMM_SMEM (3 * STAGE_BYTES)

template <int MODE>
__global__ void __launch_bounds__(256, 1)
gemm_tc(const __half* __restrict__ Ah, const __half* Al,
        const __half* B, const float* bias, float scale,
        float* __restrict__ Cf, __half* Ch, __half* Cl,
        int lda, int ldb, int ldc, int nchunk,
        long long strideA, long long strideB, long long strideC,
        const __half* B2, const float* bias2, float scale2,
        __half* Ch2, __half* Cl2)
{
    extern __shared__ char smem[];
    const uint32_t sbase = smem_u32(smem);
    const int tid = threadIdx.x;
    const int wid = tid >> 5;
    const int lane = tid & 31;
    const int wm = wid & 1;          // 0..1  M direction (64 rows each)
    const int wn = wid >> 1;         // 0..3  N direction (64 cols each)

    constexpr bool TWO_TERM = (MODE != 2);
    if (!TWO_TERM) Al = Ah;          // keeps loader simple; pass 2 skipped

    const long long z = blockIdx.z;
    if (MODE == 1) {
        if (z == 1) { B = B2; bias = bias2; scale = scale2; Ch = Ch2; Cl = Cl2; }
    } else {
        Ah += z * strideA;  Al += z * strideA;
        B  += z * strideB;
    }

    const int rowA0 = blockIdx.y * 128;
    const int colB0 = blockIdx.x * 256;

    float acc[4][8][4];
#pragma unroll
    for (int mt = 0; mt < 4; mt++)
#pragma unroll
        for (int nt = 0; nt < 8; nt++)
#pragma unroll
            for (int r = 0; r < 4; r++) acc[mt][nt][r] = 0.f;

    const __half* gAh = Ah + (size_t)rowA0 * lda;
    const __half* gAl = Al + (size_t)rowA0 * lda;
    const __half* gB  = B  + (size_t)colB0 * ldb;

    auto issue_stage = [&](int kc, int stg) {
        const uint32_t sb = sbase + stg * STAGE_BYTES;
        const int k0 = kc * 64;
#pragma unroll
        for (int it = 0; it < 4; it++) {
            int idx = it * 256 + tid;
            int r = idx >> 3, c = idx & 7;
            uint32_t so = swz(r, c);
            CP_ASYNC16(sb + A_H_OFF + so, gAh + (size_t)r * lda + k0 + c * 8);
            if (TWO_TERM)
                CP_ASYNC16(sb + A_L_OFF + so, gAl + (size_t)r * lda + k0 + c * 8);
        }
#pragma unroll
        for (int it = 0; it < 8; it++) {
            int idx = it * 256 + tid;
            int r = idx >> 3, c = idx & 7;
            uint32_t so = swz(r, c);
            CP_ASYNC16(sb + B_OFF + so, gB + (size_t)r * ldb + k0 + c * 8);
        }
    };

    issue_stage(0, 0);
    CP_COMMIT();
    if (nchunk > 1) { issue_stage(1, 1); CP_COMMIT(); }

    const int a_row = lane & 15;
    const int a_csel = lane >> 4;
    const int b_row = (lane & 7) + ((lane >> 4) << 3);
    const int b_csel = (lane >> 3) & 1;

    for (int kc = 0; kc < nchunk; kc++) {
        const int stg = kc % 3;
        if (kc + 2 < nchunk) {
            issue_stage(kc + 2, (kc + 2) % 3);
            CP_COMMIT();
            CP_WAIT2();
        } else if (kc + 1 < nchunk) {
            CP_WAIT1();
        } else {
            CP_WAIT0();
        }
        __syncthreads();

        const uint32_t sb = sbase + stg * STAGE_BYTES;
        const uint32_t aH = sb + A_H_OFF, aL = sb + A_L_OFF, bB = sb + B_OFF;

#pragma unroll
        for (int ks = 0; ks < 4; ks++) {
            uint32_t fAh[4][4], fAl[4][4], fB[4][4];
            const int kchunk = ks * 2;

#pragma unroll
            for (int mt = 0; mt < 4; mt++)
                ldsm_x4(fAh[mt], aH + swz(wm * 64 + mt * 16 + a_row, kchunk + a_csel));
#pragma unroll
            for (int g = 0; g < 4; g++)
                ldsm_x4(fB[g], bB + swz(wn * 64 + g * 16 + b_row, kchunk + b_csel));

            // pass 1: Ah * B  (32 independent accumulators)
#pragma unroll
            for (int mt = 0; mt < 4; mt++)
#pragma unroll
                for (int nt = 0; nt < 8; nt++)
                    mma16816(acc[mt][nt], fAh[mt], &fB[nt >> 1][(nt & 1) * 2]);

            if (TWO_TERM) {
#pragma unroll
                for (int mt = 0; mt < 4; mt++)
                    ldsm_x4(fAl[mt], aL + swz(wm * 64 + mt * 16 + a_row, kchunk + a_csel));
                // pass 2: Al * B
#pragma unroll
                for (int mt = 0; mt < 4; mt++)
#pragma unroll
                    for (int nt = 0; nt < 8; nt++)
                        mma16816(acc[mt][nt], fAl[mt], &fB[nt >> 1][(nt & 1) * 2]);
            }
        }
        __syncthreads();
    }

    // ------------------------------ epilogue ------------------------------
    const int lrow = (lane >> 2);
    const int lcol = (lane & 3) * 2;

#pragma unroll
    for (int mt = 0; mt < 4; mt++) {
#pragma unroll
        for (int half = 0; half < 2; half++) {
            const int row = rowA0 + wm * 64 + mt * 16 + lrow + half * 8;
            float rb = (MODE == 2) ? bias[row] : 0.f;
#pragma unroll
            for (int nt = 0; nt < 8; nt++) {
                const int col = colB0 + wn * 64 + nt * 8 + lcol;
                float v0 = acc[mt][nt][half * 2 + 0];
                float v1 = acc[mt][nt][half * 2 + 1];
                if (MODE == 0) {
                    float2 o = make_float2(v0, v1);
                    *(float2*)(Cf + z * strideC + (size_t)row * ldc + col) = o;
                } else {
                    if (MODE == 1) { v0 = (v0 + bias[col]) * scale; v1 = (v1 + bias[col + 1]) * scale; }
                    else           { v0 = v0 + rb;                 v1 = v1 + rb; }
                    __half h0 = __float2half(v0);
                    __half h1 = __float2half(v1);
                    uint32_t hw = (uint32_t)__half_as_ushort(h0) |
                                  ((uint32_t)__half_as_ushort(h1) << 16);
                    *(uint32_t*)(Ch + (size_t)row * ldc + col) = hw;
                    if (MODE == 1 && Cl != nullptr) {
                        uint32_t lw = pack_half2(v0 - __half2float(h0), v1 - __half2float(h1));
                        *(uint32_t*)(Cl + (size_t)row * ldc + col) = lw;
                    }
                }
            }
        }
    }
}

// ---------------------------------------------------------------------------
// fp32 -> (fp16 hi, fp16 lo) split
// ---------------------------------------------------------------------------
__global__ void __launch_bounds__(256, 8)
split_kernel(const float* __restrict__ in, __half* __restrict__ hi,
             __half* __restrict__ lo, size_t n)
{
    size_t i = ((size_t)blockIdx.x * blockDim.x + threadIdx.x) * 8;
    if (i >= n) return;
    float4 a = *(const float4*)(in + i);
    float4 b = *(const float4*)(in + i + 4);
    float v[8] = {a.x, a.y, a.z, a.w, b.x, b.y, b.z, b.w};
    alignas(16) uint32_t hw[4], lw[4];
#pragma unroll
    for (int c = 0; c < 8; c += 2) {
        __half h0 = __float2half(v[c]);
        __half h1 = __float2half(v[c + 1]);
        hw[c >> 1] = (uint32_t)__half_as_ushort(h0) | ((uint32_t)__half_as_ushort(h1) << 16);
        lw[c >> 1] = pack_half2(v[c] - __half2float(h0), v[c + 1] - __half2float(h1));
    }
    *(uint4*)(hi + i) = *(const uint4*)(&hw[0]);
    *(uint4*)(lo + i) = *(const uint4*)(&lw[0]);
}

// fp32 -> fp16 round only (weights / single-term operands)
__global__ void __launch_bounds__(256, 8)
convert_kernel(const float* __restrict__ in, __half* __restrict__ out, size_t n)
{
    size_t i = ((size_t)blockIdx.x * blockDim.x + threadIdx.x) * 8;
    if (i >= n) return;
    float4 a = *(const float4*)(in + i);
    float4 b = *(const float4*)(in + i + 4);
    float v[8] = {a.x, a.y, a.z, a.w, b.x, b.y, b.z, b.w};
    alignas(16) uint32_t hw[4];
#pragma unroll
    for (int c = 0; c < 8; c += 2) hw[c >> 1] = pack_half2(v[c], v[c + 1]);
    *(uint4*)(out + i) = *(const uint4*)(&hw[0]);
}

// ---------------------------------------------------------------------------
// Row softmax (fp32 in) -> split fp16 out. One block per SEQ-float row.
// ---------------------------------------------------------------------------
__global__ void __launch_bounds__(256, 4)
softmax_split(const float* __restrict__ Sm, __half* __restrict__ Ph,
              __half* __restrict__ Pl)
{
    const float* row = Sm + (size_t)blockIdx.x * SEQ;
    const int t = threadIdx.x;

    float v[8];
    *(float4*)(v + 0) = *(const float4*)(row + t * 8 + 0);
    *(float4*)(v + 4) = *(const float4*)(row + t * 8 + 4);

    float mx = v[0];
#pragma unroll
    for (int i = 1; i < 8; i++) mx = fmaxf(mx, v[i]);

    __shared__ float red[256];
    red[t] = mx;
    __syncthreads();
#pragma unroll
    for (int s = 128; s > 0; s >>= 1) {
        if (t < s) red[t] = fmaxf(red[t], red[t + s]);
        __syncthreads();
    }
    mx = red[0];
    __syncthreads();

    float sum = 0.f;
#pragma unroll
    for (int i = 0; i < 8; i++) {
        v[i] = __expf(v[i] - mx);
        sum += v[i];
    }
    red[t] = sum;
    __syncthreads();
#pragma unroll
    for (int s = 128; s > 0; s >>= 1) {
        if (t < s) red[t] += red[t + s];
        __syncthreads();
    }
    const float inv = 1.f / red[0];

    alignas(16) uint32_t hw[4], lw[4];
#pragma unroll
    for (int c = 0; c < 8; c += 2) {
        float v0 = v[c] * inv, v1 = v[c + 1] * inv;
        __half h0 = __float2half(v0);
        __half h1 = __float2half(v1);
        hw[c >> 1] = (uint32_t)__half_as_ushort(h0) | ((uint32_t)__half_as_ushort(h1) << 16);
        lw[c >> 1] = pack_half2(v0 - __half2float(h0), v1 - __half2float(h1));
    }
    size_t base = (size_t)blockIdx.x * SEQ + t * 8;
    *(uint4*)(Ph + base) = *(const uint4*)(&hw[0]);
    *(uint4*)(Pl + base) = *(const uint4*)(&lw[0]);
}

// ---------------------------------------------------------------------------
// Launch
// ---------------------------------------------------------------------------
extern "C" void kernel_launch(void* const* d_in, const int* in_sizes, int n_in,
                              void* d_out, int out_size)
{
    const float* x  = (const float*)d_in[0];
    const float* Wq = (const float*)d_in[1];
    const float* bq = (const float*)d_in[2];
    const float* Wk = (const float*)d_in[3];
    const float* bk = (const float*)d_in[4];
    const float* Wv = (const float*)d_in[5];
    const float* bv = (const float*)d_in[6];
    float* out = (float*)d_out;

    cudaFuncSetAttribute((const void*)gemm_tc<0>, cudaFuncAttributeMaxDynamicSharedMemorySize, GEMM_SMEM);
    cudaFuncSetAttribute((const void*)gemm_tc<1>, cudaFuncAttributeMaxDynamicSharedMemorySize, GEMM_SMEM);
    cudaFuncSetAttribute((const void*)gemm_tc<2>, cudaFuncAttributeMaxDynamicSharedMemorySize, GEMM_SMEM);

    __half *xh, *xl, *pWq, *pWk, *pWv, *Qh, *Ql, *Kh, *Vth, *Ph, *Pl;
    float* Sp;
    cudaGetSymbolAddress((void**)&xh, g_xh);   cudaGetSymbolAddress((void**)&xl, g_xl);
    cudaGetSymbolAddress((void**)&pWq, g_Wq);  cudaGetSymbolAddress((void**)&pWk, g_Wk);
    cudaGetSymbolAddress((void**)&pWv, g_Wv);
    cudaGetSymbolAddress((void**)&Qh, g_Qh);   cudaGetSymbolAddress((void**)&Ql, g_Ql);
    cudaGetSymbolAddress((void**)&Kh, g_Kh);
    cudaGetSymbolAddress((void**)&Vth, g_Vth);
    cudaGetSymbolAddress((void**)&Ph, g_Ph);   cudaGetSymbolAddress((void**)&Pl, g_Pl);
    cudaGetSymbolAddress((void**)&Sp, g_S);

    const float qscale = 0.03125f;   // 1/sqrt(1024), exact power of two

    // 1) prepare fp16 operands
    split_kernel<<<(size_t)BS * EMBED / 2048, 256>>>(x, xh, xl, (size_t)BS * EMBED);
    convert_kernel<<<EMBED * EMBED / 2048, 256>>>(Wq, pWq, (size_t)EMBED * EMBED);
    convert_kernel<<<EMBED * EMBED / 2048, 256>>>(Wk, pWk, (size_t)EMBED * EMBED);
    convert_kernel<<<EMBED * EMBED / 2048, 256>>>(Wv, pWv, (size_t)EMBED * EMBED);

    // 2) Q = (x Wq^T + bq)*qscale -> Qh,Ql (z=0) ;  K = x Wk^T + bk -> Kh (z=1)
    {
        dim3 grid(EMBED / 256, BS / 128, 2);
        gemm_tc<1><<<grid, 256, GEMM_SMEM>>>(xh, xl, pWq, bq, qscale,
                                             nullptr, Qh, Ql,
                                             EMBED, EMBED, EMBED, EMBED / 64, 0, 0, 0,
                                             pWk, bk, 1.0f, Kh, nullptr);
    }
    // 3) Vt[e, bs] = Wv x^T + bv (row bias), single-term A, ldc = BS
    {
        dim3 grid(BS / 256, EMBED / 128, 1);
        gemm_tc<2><<<grid, 256, GEMM_SMEM>>>(pWv, pWv, xh, bv, 1.0f,
                                             nullptr, Vth, nullptr,
                                             EMBED, EMBED, BS, EMBED / 64, 0, 0, 0,
                                             nullptr, nullptr, 0.f, nullptr, nullptr);
    }
    // 4) scores = Q K^T (scale folded into Q), batched, fp32 out
    {
        dim3 grid(SEQ / 256, SEQ / 128, BATCH);
        gemm_tc<0><<<grid, 256, GEMM_SMEM>>>(Qh, Ql, Kh, nullptr, 1.0f,
                                             Sp, nullptr, nullptr,
                                             EMBED, EMBED, SEQ, EMBED / 64,
                                             (long long)SEQ * EMBED,
                                             (long long)SEQ * EMBED,
                                             (long long)SEQ * SEQ,
                                             nullptr, nullptr, 0.f, nullptr, nullptr);
    }
    // 5) softmax -> split fp16 P
    softmax_split<<<BATCH * SEQ, 256>>>(Sp, Ph, Pl);

    // 6) out = P V (B = Vt rows, per-batch column window), fp32 out
    {
        dim3 grid(EMBED / 256, SEQ / 128, BATCH);
        gemm_tc<0><<<grid, 256, GEMM_SMEM>>>(Ph, Pl, Vth, nullptr, 1.0f,
                                             out, nullptr, nullptr,
                                             SEQ, BS, EMBED, SEQ / 64,
                                             (long long)SEQ * SEQ,
                                             (long long)SEQ,
                                             (long long)SEQ * EMBED,
                                             nullptr, nullptr, 0.f, nullptr, nullptr);
    }
}

// round 8
// speedup vs baseline: 1.7172x; 1.1454x over previous
#include <cuda_runtime.h>
#include <cuda_fp16.h>
#include <cstdint>
#include <math.h>

#define BATCH 8
#define SEQ   2048
#define EMBED 1024
#define BS    (BATCH * SEQ)          // 16384

// ---------------------------------------------------------------------------
// Device-global scratch (allocation-free rule)
// ---------------------------------------------------------------------------
__device__ __half g_xh[(size_t)BS * EMBED];
__device__ __half g_xl[(size_t)BS * EMBED];
__device__ __half g_Wq[EMBED * EMBED];
__device__ __half g_Wk[EMBED * EMBED];
__device__ __half g_Wv[EMBED * EMBED];
__device__ __half g_Qh[(size_t)BS * EMBED], g_Ql[(size_t)BS * EMBED];
__device__ __half g_Kh[(size_t)BS * EMBED];
__device__ __half g_Vth[(size_t)EMBED * BS];   // V pre-transposed [EMBED][BS]
__device__ float  g_S[(size_t)BATCH * SEQ * SEQ];
__device__ __half g_Ph[(size_t)BATCH * SEQ * SEQ];

// ---------------------------------------------------------------------------
// Helpers
// ---------------------------------------------------------------------------
__device__ __forceinline__ uint32_t smem_u32(const void* p) {
    uint32_t a;
    asm("{ .reg .u64 t; cvta.to.shared.u64 t, %1; cvt.u32.u64 %0, t; }" : "=r"(a) : "l"(p));
    return a;
}

#define CP_ASYNC16(sm, gp) \
    asm volatile("cp.async.cg.shared.global [%0], [%1], 16;" :: "r"(sm), "l"(gp) : "memory")
#define CP_COMMIT()  asm volatile("cp.async.commit_group;" ::: "memory")
#define CP_WAIT0()   asm volatile("cp.async.wait_group 0;" ::: "memory")
#define CP_WAIT1()   asm volatile("cp.async.wait_group 1;" ::: "memory")
#define CP_WAIT2()   asm volatile("cp.async.wait_group 2;" ::: "memory")

__device__ __forceinline__ void ldsm_x4(uint32_t* r, uint32_t addr) {
    asm volatile("ldmatrix.sync.aligned.m8n8.x4.shared.b16 {%0,%1,%2,%3}, [%4];"
                 : "=r"(r[0]), "=r"(r[1]), "=r"(r[2]), "=r"(r[3]) : "r"(addr));
}

__device__ __forceinline__ void mma16816(float* c, const uint32_t* a, const uint32_t* b) {
    asm volatile(
        "mma.sync.aligned.m16n8k16.row.col.f32.f16.f16.f32 "
        "{%0,%1,%2,%3}, {%4,%5,%6,%7}, {%8,%9}, {%0,%1,%2,%3};"
        : "+f"(c[0]), "+f"(c[1]), "+f"(c[2]), "+f"(c[3])
        : "r"(a[0]), "r"(a[1]), "r"(a[2]), "r"(a[3]), "r"(b[0]), "r"(b[1]));
}

// byte offset of 16B chunk (row, c) inside a [rows][64 fp16] tile, xor-swizzled
__device__ __forceinline__ uint32_t swz(int row, int c) {
    return (uint32_t)((row * 8 + (c ^ (row & 7))) * 16);
}

__device__ __forceinline__ uint32_t pack_half2(float v0, float v1) {
    __half h0 = __float2half(v0), h1 = __float2half(v1);
    return (uint32_t)__half_as_ushort(h0) | ((uint32_t)__half_as_ushort(h1) << 16);
}

// ---------------------------------------------------------------------------
// HMMA GEMM NT: C[M,N] = (Ah[+Al])[M,K] * B[N,K]^T, fp16 in, fp32 accum.
// CTA tile 128x256, warp tile 64x64 (8 warps, 2x4), K-chunk 64,
// 3-stage cp.async pipeline (64KB/stage).
// MODE 0: C -> fp32 Cf
// MODE 1: v=(acc+bias[col])*scale -> Ch (+Cl if non-null);
//         blockIdx.z picks {B,bias,scale,Ch,Cl} (z=0) or the "2" set (z=1)
// MODE 2: v=acc+bias[row] -> Ch only
// TWO_TERM: whether A has a lo component (Al) accumulated in a second pass.
// ---------------------------------------------------------------------------
#define STAGE_BYTES 65536
#define A_H_OFF 0
#define A_L_OFF 16384
#define B_OFF   32768
#define GEMM_SMEM (3 * STAGE_BYTES)

template <int MODE, bool TWO_TERM>
__global__ void __launch_bounds__(256, 1)
gemm_tc(const __half* __restrict__ Ah, const __half* Al,
        const __half* B, const float* bias, float scale,
        float* __restrict__ Cf, __half* Ch, __half* Cl,
        int lda, int ldb, int ldc, int nchunk,
        long long strideA, long long strideB, long long strideC,
        const __half* B2, const float* bias2, float scale2,
        __half* Ch2, __half* Cl2)
{
    extern __shared__ char smem[];
    const uint32_t sbase = smem_u32(smem);
    const int tid = threadIdx.x;
    const int wid = tid >> 5;
    const int lane = tid & 31;
    const int wm = wid & 1;          // 0..1  M direction (64 rows each)
    const int wn = wid >> 1;         // 0..3  N direction (64 cols each)

    if (!TWO_TERM) Al = Ah;          // unused path; keeps pointer math valid

    const long long z = blockIdx.z;
    if (MODE == 1) {
        if (z == 1) { B = B2; bias = bias2; scale = scale2; Ch = Ch2; Cl = Cl2; }
    } else {
        Ah += z * strideA;  Al += z * strideA;
        B  += z * strideB;
    }

    const int rowA0 = blockIdx.y * 128;
    const int colB0 = blockIdx.x * 256;

    float acc[4][8][4];
#pragma unroll
    for (int mt = 0; mt < 4; mt++)
#pragma unroll
        for (int nt = 0; nt < 8; nt++)
#pragma unroll
            for (int r = 0; r < 4; r++) acc[mt][nt][r] = 0.f;

    const __half* gAh = Ah + (size_t)rowA0 * lda;
    const __half* gAl = Al + (size_t)rowA0 * lda;
    const __half* gB  = B  + (size_t)colB0 * ldb;

    auto issue_stage = [&](int kc, int stg) {
        const uint32_t sb = sbase + stg * STAGE_BYTES;
        const int k0 = kc * 64;
#pragma unroll
        for (int it = 0; it < 4; it++) {
            int idx = it * 256 + tid;
            int r = idx >> 3, c = idx & 7;
            uint32_t so = swz(r, c);
            CP_ASYNC16(sb + A_H_OFF + so, gAh + (size_t)r * lda + k0 + c * 8);
            if (TWO_TERM)
                CP_ASYNC16(sb + A_L_OFF + so, gAl + (size_t)r * lda + k0 + c * 8);
        }
#pragma unroll
        for (int it = 0; it < 8; it++) {
            int idx = it * 256 + tid;
            int r = idx >> 3, c = idx & 7;
            uint32_t so = swz(r, c);
            CP_ASYNC16(sb + B_OFF + so, gB + (size_t)r * ldb + k0 + c * 8);
        }
    };

    issue_stage(0, 0);
    CP_COMMIT();
    if (nchunk > 1) { issue_stage(1, 1); CP_COMMIT(); }

    const int a_row = lane & 15;
    const int a_csel = lane >> 4;
    const int b_row = (lane & 7) + ((lane >> 4) << 3);
    const int b_csel = (lane >> 3) & 1;

    for (int kc = 0; kc < nchunk; kc++) {
        const int stg = kc % 3;
        if (kc + 2 < nchunk) {
            issue_stage(kc + 2, (kc + 2) % 3);
            CP_COMMIT();
            CP_WAIT2();
        } else if (kc + 1 < nchunk) {
            CP_WAIT1();
        } else {
            CP_WAIT0();
        }
        __syncthreads();

        const uint32_t sb = sbase + stg * STAGE_BYTES;
        const uint32_t aH = sb + A_H_OFF, aL = sb + A_L_OFF, bB = sb + B_OFF;

#pragma unroll
        for (int ks = 0; ks < 4; ks++) {
            uint32_t fAh[4][4], fAl[4][4], fB[4][4];
            const int kchunk = ks * 2;

#pragma unroll
            for (int mt = 0; mt < 4; mt++)
                ldsm_x4(fAh[mt], aH + swz(wm * 64 + mt * 16 + a_row, kchunk + a_csel));
#pragma unroll
            for (int g = 0; g < 4; g++)
                ldsm_x4(fB[g], bB + swz(wn * 64 + g * 16 + b_row, kchunk + b_csel));

            // pass 1: Ah * B  (32 independent accumulators)
#pragma unroll
            for (int mt = 0; mt < 4; mt++)
#pragma unroll
                for (int nt = 0; nt < 8; nt++)
                    mma16816(acc[mt][nt], fAh[mt], &fB[nt >> 1][(nt & 1) * 2]);

            if (TWO_TERM) {
#pragma unroll
                for (int mt = 0; mt < 4; mt++)
                    ldsm_x4(fAl[mt], aL + swz(wm * 64 + mt * 16 + a_row, kchunk + a_csel));
                // pass 2: Al * B
#pragma unroll
                for (int mt = 0; mt < 4; mt++)
#pragma unroll
                    for (int nt = 0; nt < 8; nt++)
                        mma16816(acc[mt][nt], fAl[mt], &fB[nt >> 1][(nt & 1) * 2]);
            }
        }
        __syncthreads();
    }

    // ------------------------------ epilogue ------------------------------
    const int lrow = (lane >> 2);
    const int lcol = (lane & 3) * 2;

#pragma unroll
    for (int mt = 0; mt < 4; mt++) {
#pragma unroll
        for (int half = 0; half < 2; half++) {
            const int row = rowA0 + wm * 64 + mt * 16 + lrow + half * 8;
            float rb = (MODE == 2) ? bias[row] : 0.f;
#pragma unroll
            for (int nt = 0; nt < 8; nt++) {
                const int col = colB0 + wn * 64 + nt * 8 + lcol;
                float v0 = acc[mt][nt][half * 2 + 0];
                float v1 = acc[mt][nt][half * 2 + 1];
                if (MODE == 0) {
                    float2 o = make_float2(v0, v1);
                    *(float2*)(Cf + z * strideC + (size_t)row * ldc + col) = o;
                } else {
                    if (MODE == 1) { v0 = (v0 + bias[col]) * scale; v1 = (v1 + bias[col + 1]) * scale; }
                    else           { v0 = v0 + rb;                 v1 = v1 + rb; }
                    __half h0 = __float2half(v0);
                    __half h1 = __float2half(v1);
                    uint32_t hw = (uint32_t)__half_as_ushort(h0) |
                                  ((uint32_t)__half_as_ushort(h1) << 16);
                    *(uint32_t*)(Ch + (size_t)row * ldc + col) = hw;
                    if (MODE == 1 && Cl != nullptr) {
                        uint32_t lw = pack_half2(v0 - __half2float(h0), v1 - __half2float(h1));
                        *(uint32_t*)(Cl + (size_t)row * ldc + col) = lw;
                    }
                }
            }
        }
    }
}

// ---------------------------------------------------------------------------
// fp32 -> (fp16 hi, fp16 lo) split
// ---------------------------------------------------------------------------
__global__ void __launch_bounds__(256, 8)
split_kernel(const float* __restrict__ in, __half* __restrict__ hi,
             __half* __restrict__ lo, size_t n)
{
    size_t i = ((size_t)blockIdx.x * blockDim.x + threadIdx.x) * 8;
    if (i >= n) return;
    float4 a = *(const float4*)(in + i);
    float4 b = *(const float4*)(in + i + 4);
    float v[8] = {a.x, a.y, a.z, a.w, b.x, b.y, b.z, b.w};
    alignas(16) uint32_t hw[4], lw[4];
#pragma unroll
    for (int c = 0; c < 8; c += 2) {
        __half h0 = __float2half(v[c]);
        __half h1 = __float2half(v[c + 1]);
        hw[c >> 1] = (uint32_t)__half_as_ushort(h0) | ((uint32_t)__half_as_ushort(h1) << 16);
        lw[c >> 1] = pack_half2(v[c] - __half2float(h0), v[c + 1] - __half2float(h1));
    }
    *(uint4*)(hi + i) = *(const uint4*)(&hw[0]);
    *(uint4*)(lo + i) = *(const uint4*)(&lw[0]);
}

// fp32 -> fp16 round only (weights / single-term operands)
__global__ void __launch_bounds__(256, 8)
convert_kernel(const float* __restrict__ in, __half* __restrict__ out, size_t n)
{
    size_t i = ((size_t)blockIdx.x * blockDim.x + threadIdx.x) * 8;
    if (i >= n) return;
    float4 a = *(const float4*)(in + i);
    float4 b = *(const float4*)(in + i + 4);
    float v[8] = {a.x, a.y, a.z, a.w, b.x, b.y, b.z, b.w};
    alignas(16) uint32_t hw[4];
#pragma unroll
    for (int c = 0; c < 8; c += 2) hw[c >> 1] = pack_half2(v[c], v[c + 1]);
    *(uint4*)(out + i) = *(const uint4*)(&hw[0]);
}

// ---------------------------------------------------------------------------
// Row softmax (fp32 in) -> fp16 out (single term). One block per SEQ row.
// ---------------------------------------------------------------------------
__global__ void __launch_bounds__(256, 4)
softmax_h(const float* __restrict__ Sm, __half* __restrict__ Ph)
{
    const float* row = Sm + (size_t)blockIdx.x * SEQ;
    const int t = threadIdx.x;

    float v[8];
    *(float4*)(v + 0) = *(const float4*)(row + t * 8 + 0);
    *(float4*)(v + 4) = *(const float4*)(row + t * 8 + 4);

    float mx = v[0];
#pragma unroll
    for (int i = 1; i < 8; i++) mx = fmaxf(mx, v[i]);

    __shared__ float red[256];
    red[t] = mx;
    __syncthreads();
#pragma unroll
    for (int s = 128; s > 0; s >>= 1) {
        if (t < s) red[t] = fmaxf(red[t], red[t + s]);
        __syncthreads();
    }
    mx = red[0];
    __syncthreads();

    float sum = 0.f;
#pragma unroll
    for (int i = 0; i < 8; i++) {
        v[i] = __expf(v[i] - mx);
        sum += v[i];
    }
    red[t] = sum;
    __syncthreads();
#pragma unroll
    for (int s = 128; s > 0; s >>= 1) {
        if (t < s) red[t] += red[t + s];
        __syncthreads();
    }
    const float inv = 1.f / red[0];

    alignas(16) uint32_t hw[4];
#pragma unroll
    for (int c = 0; c < 8; c += 2)
        hw[c >> 1] = pack_half2(v[c] * inv, v[c + 1] * inv);
    size_t base = (size_t)blockIdx.x * SEQ + t * 8;
    *(uint4*)(Ph + base) = *(const uint4*)(&hw[0]);
}

// ---------------------------------------------------------------------------
// Launch
// ---------------------------------------------------------------------------
extern "C" void kernel_launch(void* const* d_in, const int* in_sizes, int n_in,
                              void* d_out, int out_size)
{
    const float* x  = (const float*)d_in[0];
    const float* Wq = (const float*)d_in[1];
    const float* bq = (const float*)d_in[2];
    const float* Wk = (const float*)d_in[3];
    const float* bk = (const float*)d_in[4];
    const float* Wv = (const float*)d_in[5];
    const float* bv = (const float*)d_in[6];
    float* out = (float*)d_out;

    cudaFuncSetAttribute((const void*)gemm_tc<0, true>,  cudaFuncAttributeMaxDynamicSharedMemorySize, GEMM_SMEM);
    cudaFuncSetAttribute((const void*)gemm_tc<0, false>, cudaFuncAttributeMaxDynamicSharedMemorySize, GEMM_SMEM);
    cudaFuncSetAttribute((const void*)gemm_tc<1, true>,  cudaFuncAttributeMaxDynamicSharedMemorySize, GEMM_SMEM);
    cudaFuncSetAttribute((const void*)gemm_tc<2, false>, cudaFuncAttributeMaxDynamicSharedMemorySize, GEMM_SMEM);

    __half *xh, *xl, *pWq, *pWk, *pWv, *Qh, *Ql, *Kh, *Vth, *Ph;
    float* Sp;
    cudaGetSymbolAddress((void**)&xh, g_xh);   cudaGetSymbolAddress((void**)&xl, g_xl);
    cudaGetSymbolAddress((void**)&pWq, g_Wq);  cudaGetSymbolAddress((void**)&pWk, g_Wk);
    cudaGetSymbolAddress((void**)&pWv, g_Wv);
    cudaGetSymbolAddress((void**)&Qh, g_Qh);   cudaGetSymbolAddress((void**)&Ql, g_Ql);
    cudaGetSymbolAddress((void**)&Kh, g_Kh);
    cudaGetSymbolAddress((void**)&Vth, g_Vth);
    cudaGetSymbolAddress((void**)&Ph, g_Ph);
    cudaGetSymbolAddress((void**)&Sp, g_S);

    const float qscale = 0.03125f;   // 1/sqrt(1024), exact power of two

    // 1) prepare fp16 operands
    split_kernel<<<(size_t)BS * EMBED / 2048, 256>>>(x, xh, xl, (size_t)BS * EMBED);
    convert_kernel<<<EMBED * EMBED / 2048, 256>>>(Wq, pWq, (size_t)EMBED * EMBED);
    convert_kernel<<<EMBED * EMBED / 2048, 256>>>(Wk, pWk, (size_t)EMBED * EMBED);
    convert_kernel<<<EMBED * EMBED / 2048, 256>>>(Wv, pWv, (size_t)EMBED * EMBED);

    // 2) Q = (x Wq^T + bq)*qscale -> Qh,Ql (z=0) ;  K = x Wk^T + bk -> Kh (z=1)
    {
        dim3 grid(EMBED / 256, BS / 128, 2);
        gemm_tc<1, true><<<grid, 256, GEMM_SMEM>>>(xh, xl, pWq, bq, qscale,
                                                   nullptr, Qh, Ql,
                                                   EMBED, EMBED, EMBED, EMBED / 64, 0, 0, 0,
                                                   pWk, bk, 1.0f, Kh, nullptr);
    }
    // 3) Vt[e, bs] = Wv x^T + bv (row bias), single-term A, ldc = BS
    {
        dim3 grid(BS / 256, EMBED / 128, 1);
        gemm_tc<2, false><<<grid, 256, GEMM_SMEM>>>(pWv, nullptr, xh, bv, 1.0f,
                                                    nullptr, Vth, nullptr,
                                                    EMBED, EMBED, BS, EMBED / 64, 0, 0, 0,
                                                    nullptr, nullptr, 0.f, nullptr, nullptr);
    }
    // 4) scores = Q K^T (scale folded into Q), batched, fp32 out, two-term Q
    {
        dim3 grid(SEQ / 256, SEQ / 128, BATCH);
        gemm_tc<0, true><<<grid, 256, GEMM_SMEM>>>(Qh, Ql, Kh, nullptr, 1.0f,
                                                   Sp, nullptr, nullptr,
                                                   EMBED, EMBED, SEQ, EMBED / 64,
                                                   (long long)SEQ * EMBED,
                                                   (long long)SEQ * EMBED,
                                                   (long long)SEQ * SEQ,
                                                   nullptr, nullptr, 0.f, nullptr, nullptr);
    }
    // 5) softmax -> fp16 P (single term)
    softmax_h<<<BATCH * SEQ, 256>>>(Sp, Ph);

    // 6) out = P V (B = Vt rows, per-batch column window), fp32 out, single-term P
    {
        dim3 grid(EMBED / 256, SEQ / 128, BATCH);
        gemm_tc<0, false><<<grid, 256, GEMM_SMEM>>>(Ph, nullptr, Vth, nullptr, 1.0f,
                                                    out, nullptr, nullptr,
                                                    SEQ, BS, EMBED, SEQ / 64,
                                                    (long long)SEQ * SEQ,
                                                    (long long)SEQ,
                                                    (long long)SEQ * EMBED,
                                                    nullptr, nullptr, 0.f, nullptr, nullptr);
    }
}

// round 9
// speedup vs baseline: 2.3136x; 1.3473x over previous
#include <cuda_runtime.h>
#include <cuda_fp16.h>
#include <cstdint>
#include <math.h>

#define BATCH 8
#define SEQ   2048
#define EMBED 1024
#define BS    (BATCH * SEQ)          // 16384

// ---------------------------------------------------------------------------
// Device-global scratch (allocation-free rule) — all single-term fp16 now
// ---------------------------------------------------------------------------
__device__ __half g_xh[(size_t)BS * EMBED];
__device__ __half g_Wq[EMBED * EMBED];
__device__ __half g_Wk[EMBED * EMBED];
__device__ __half g_Wv[EMBED * EMBED];
__device__ __half g_Qh[(size_t)BS * EMBED];
__device__ __half g_Kh[(size_t)BS * EMBED];
__device__ __half g_Vth[(size_t)EMBED * BS];   // V pre-transposed [EMBED][BS]
__device__ float  g_S[(size_t)BATCH * SEQ * SEQ];
__device__ __half g_Ph[(size_t)BATCH * SEQ * SEQ];

// ---------------------------------------------------------------------------
// Helpers
// ---------------------------------------------------------------------------
__device__ __forceinline__ uint32_t smem_u32(const void* p) {
    uint32_t a;
    asm("{ .reg .u64 t; cvta.to.shared.u64 t, %1; cvt.u32.u64 %0, t; }" : "=r"(a) : "l"(p));
    return a;
}

#define CP_ASYNC16(sm, gp) \
    asm volatile("cp.async.cg.shared.global [%0], [%1], 16;" :: "r"(sm), "l"(gp) : "memory")
#define CP_COMMIT()  asm volatile("cp.async.commit_group;" ::: "memory")
#define CP_WAITN(n)  asm volatile("cp.async.wait_group %0;" :: "n"(n) : "memory")

__device__ __forceinline__ void ldsm_x4(uint32_t* r, uint32_t addr) {
    asm volatile("ldmatrix.sync.aligned.m8n8.x4.shared.b16 {%0,%1,%2,%3}, [%4];"
                 : "=r"(r[0]), "=r"(r[1]), "=r"(r[2]), "=r"(r[3]) : "r"(addr));
}

__device__ __forceinline__ void mma16816(float* c, const uint32_t* a, const uint32_t* b) {
    asm volatile(
        "mma.sync.aligned.m16n8k16.row.col.f32.f16.f16.f32 "
        "{%0,%1,%2,%3}, {%4,%5,%6,%7}, {%8,%9}, {%0,%1,%2,%3};"
        : "+f"(c[0]), "+f"(c[1]), "+f"(c[2]), "+f"(c[3])
        : "r"(a[0]), "r"(a[1]), "r"(a[2]), "r"(a[3]), "r"(b[0]), "r"(b[1]));
}

// byte offset of 16B chunk (row, c) inside a [rows][64 fp16] tile, xor-swizzled
__device__ __forceinline__ uint32_t swz(int row, int c) {
    return (uint32_t)((row * 8 + (c ^ (row & 7))) * 16);
}

__device__ __forceinline__ uint32_t pack_half2(float v0, float v1) {
    __half h0 = __float2half(v0), h1 = __float2half(v1);
    return (uint32_t)__half_as_ushort(h0) | ((uint32_t)__half_as_ushort(h1) << 16);
}

// ---------------------------------------------------------------------------
// HMMA GEMM NT: C[M,N] = A[M,K] * B[N,K]^T, fp16 in, fp32 accum.
// CTA tile 128x256, warp tile 64x64 (8 warps, 2x4), K-chunk 64,
// 4-stage cp.async pipeline (48KB/stage).
// MODE 0: C -> fp32 Cf
// MODE 1: v=(acc+bias[col])*scale -> fp16 Ch;
//         blockIdx.z picks {B,bias,scale,Ch} (z=0) or the "2" set (z=1)
// MODE 2: v=acc+bias[row] -> fp16 Ch
// ---------------------------------------------------------------------------
#define STAGE_BYTES 49152
#define A_OFF 0
#define B_OFF 16384
#define NSTAGE 4
#define GEMM_SMEM (NSTAGE * STAGE_BYTES)

template <int MODE>
__global__ void __launch_bounds__(256, 1)
gemm_tc(const __half* __restrict__ Ah,
        const __half* B, const float* bias, float scale,
        float* __restrict__ Cf, __half* Ch,
        int lda, int ldb, int ldc, int nchunk,
        long long strideA, long long strideB, long long strideC,
        const __half* B2, const float* bias2, float scale2, __half* Ch2)
{
    extern __shared__ char smem[];
    const uint32_t sbase = smem_u32(smem);
    const int tid = threadIdx.x;
    const int wid = tid >> 5;
    const int lane = tid & 31;
    const int wm = wid & 1;          // 0..1  M direction (64 rows each)
    const int wn = wid >> 1;         // 0..3  N direction (64 cols each)

    const long long z = blockIdx.z;
    if (MODE == 1) {
        if (z == 1) { B = B2; bias = bias2; scale = scale2; Ch = Ch2; }
    } else {
        Ah += z * strideA;
        B  += z * strideB;
    }

    const int rowA0 = blockIdx.y * 128;
    const int colB0 = blockIdx.x * 256;

    float acc[4][8][4];
#pragma unroll
    for (int mt = 0; mt < 4; mt++)
#pragma unroll
        for (int nt = 0; nt < 8; nt++)
#pragma unroll
            for (int r = 0; r < 4; r++) acc[mt][nt][r] = 0.f;

    const __half* gA = Ah + (size_t)rowA0 * lda;
    const __half* gB = B  + (size_t)colB0 * ldb;

    // one stage: A 128x64 fp16 (16KB), B 256x64 fp16 (32KB)
    auto issue_stage = [&](int kc, int stg) {
        const uint32_t sb = sbase + stg * STAGE_BYTES;
        const int k0 = kc * 64;
#pragma unroll
        for (int it = 0; it < 2; it++) {
            int idx = it * 256 + tid;
            int r = idx >> 2, c4 = idx & 3;            // 128 rows x 4 chunks... wait
            (void)r; (void)c4;
        }
        // A: 512 chunks (128 rows x 4? no: 128 rows x 8 chunks of 16B? 64 fp16 =
        // 128B = 8 chunks). 128*8=1024 chunks? No: 64 fp16 per row = 128 bytes =
        // 8 x 16B. 128 rows -> 1024 chunks. Hmm that's 4 per thread.
#pragma unroll
        for (int it = 0; it < 4; it++) {
            int idx = it * 256 + tid;
            int r = idx >> 3, c = idx & 7;
            uint32_t so = swz(r, c);
            CP_ASYNC16(sb + A_OFF + so, gA + (size_t)r * lda + k0 + c * 8);
        }
#pragma unroll
        for (int it = 0; it < 8; it++) {
            int idx = it * 256 + tid;
            int r = idx >> 3, c = idx & 7;
            uint32_t so = swz(r, c);
            CP_ASYNC16(sb + B_OFF + so, gB + (size_t)r * ldb + k0 + c * 8);
        }
    };

    // NOTE on A tile size: A is 128 rows x 64 fp16 = 128 rows x 8 chunks = 1024
    // chunks = 16KB. The loop above issues 4 chunks/thread (1024 total). Correct.

    issue_stage(0, 0); CP_COMMIT();
    if (nchunk > 1) { issue_stage(1, 1); CP_COMMIT(); }
    if (nchunk > 2) { issue_stage(2, 2); CP_COMMIT(); }

    const int a_row = lane & 15;
    const int a_csel = lane >> 4;
    const int b_row = (lane & 7) + ((lane >> 4) << 3);
    const int b_csel = (lane >> 3) & 1;

    for (int kc = 0; kc < nchunk; kc++) {
        const int stg = kc & 3;
        const int ahead = nchunk - 1 - kc;     // stages after this one
        if (kc + 3 < nchunk) {
            issue_stage(kc + 3, (kc + 3) & 3);
            CP_COMMIT();
            CP_WAITN(3);
        } else if (ahead == 2) {
            CP_WAITN(2);
        } else if (ahead == 1) {
            CP_WAITN(1);
        } else {
            CP_WAITN(0);
        }
        __syncthreads();

        const uint32_t sb = sbase + stg * STAGE_BYTES;
        const uint32_t aA = sb + A_OFF, bB = sb + B_OFF;

#pragma unroll
        for (int ks = 0; ks < 4; ks++) {
            uint32_t fA[4][4], fB[4][4];
            const int kchunk = ks * 2;

#pragma unroll
            for (int mt = 0; mt < 4; mt++)
                ldsm_x4(fA[mt], aA + swz(wm * 64 + mt * 16 + a_row, kchunk + a_csel));
#pragma unroll
            for (int g = 0; g < 4; g++)
                ldsm_x4(fB[g], bB + swz(wn * 64 + g * 16 + b_row, kchunk + b_csel));

#pragma unroll
            for (int mt = 0; mt < 4; mt++)
#pragma unroll
                for (int nt = 0; nt < 8; nt++)
                    mma16816(acc[mt][nt], fA[mt], &fB[nt >> 1][(nt & 1) * 2]);
        }
        __syncthreads();
    }

    // ------------------------------ epilogue ------------------------------
    const int lrow = (lane >> 2);
    const int lcol = (lane & 3) * 2;

#pragma unroll
    for (int mt = 0; mt < 4; mt++) {
#pragma unroll
        for (int half = 0; half < 2; half++) {
            const int row = rowA0 + wm * 64 + mt * 16 + lrow + half * 8;
            float rb = (MODE == 2) ? bias[row] : 0.f;
#pragma unroll
            for (int nt = 0; nt < 8; nt++) {
                const int col = colB0 + wn * 64 + nt * 8 + lcol;
                float v0 = acc[mt][nt][half * 2 + 0];
                float v1 = acc[mt][nt][half * 2 + 1];
                if (MODE == 0) {
                    float2 o = make_float2(v0, v1);
                    *(float2*)(Cf + z * strideC + (size_t)row * ldc + col) = o;
                } else {
                    if (MODE == 1) { v0 = (v0 + bias[col]) * scale; v1 = (v1 + bias[col + 1]) * scale; }
                    else           { v0 = v0 + rb;                 v1 = v1 + rb; }
                    *(uint32_t*)(Ch + (size_t)row * ldc + col) = pack_half2(v0, v1);
                }
            }
        }
    }
}

// ---------------------------------------------------------------------------
// fp32 -> fp16 round
// ---------------------------------------------------------------------------
__global__ void __launch_bounds__(256, 8)
convert_kernel(const float* __restrict__ in, __half* __restrict__ out, size_t n)
{
    size_t i = ((size_t)blockIdx.x * blockDim.x + threadIdx.x) * 8;
    if (i >= n) return;
    float4 a = *(const float4*)(in + i);
    float4 b = *(const float4*)(in + i + 4);
    float v[8] = {a.x, a.y, a.z, a.w, b.x, b.y, b.z, b.w};
    alignas(16) uint32_t hw[4];
#pragma unroll
    for (int c = 0; c < 8; c += 2) hw[c >> 1] = pack_half2(v[c], v[c + 1]);
    *(uint4*)(out + i) = *(const uint4*)(&hw[0]);
}

// ---------------------------------------------------------------------------
// Row softmax (fp32 in) -> fp16 out. One block per SEQ row.
// ---------------------------------------------------------------------------
__global__ void __launch_bounds__(256, 4)
softmax_h(const float* __restrict__ Sm, __half* __restrict__ Ph)
{
    const float* row = Sm + (size_t)blockIdx.x * SEQ;
    const int t = threadIdx.x;

    float v[8];
    *(float4*)(v + 0) = *(const float4*)(row + t * 8 + 0);
    *(float4*)(v + 4) = *(const float4*)(row + t * 8 + 4);

    float mx = v[0];
#pragma unroll
    for (int i = 1; i < 8; i++) mx = fmaxf(mx, v[i]);

    __shared__ float red[256];
    red[t] = mx;
    __syncthreads();
#pragma unroll
    for (int s = 128; s > 0; s >>= 1) {
        if (t < s) red[t] = fmaxf(red[t], red[t + s]);
        __syncthreads();
    }
    mx = red[0];
    __syncthreads();

    float sum = 0.f;
#pragma unroll
    for (int i = 0; i < 8; i++) {
        v[i] = __expf(v[i] - mx);
        sum += v[i];
    }
    red[t] = sum;
    __syncthreads();
#pragma unroll
    for (int s = 128; s > 0; s >>= 1) {
        if (t < s) red[t] += red[t + s];
        __syncthreads();
    }
    const float inv = 1.f / red[0];

    alignas(16) uint32_t hw[4];
#pragma unroll
    for (int c = 0; c < 8; c += 2)
        hw[c >> 1] = pack_half2(v[c] * inv, v[c + 1] * inv);
    size_t base = (size_t)blockIdx.x * SEQ + t * 8;
    *(uint4*)(Ph + base) = *(const uint4*)(&hw[0]);
}

// ---------------------------------------------------------------------------
// Launch
// ---------------------------------------------------------------------------
extern "C" void kernel_launch(void* const* d_in, const int* in_sizes, int n_in,
                              void* d_out, int out_size)
{
    const float* x  = (const float*)d_in[0];
    const float* Wq = (const float*)d_in[1];
    const float* bq = (const float*)d_in[2];
    const float* Wk = (const float*)d_in[3];
    const float* bk = (const float*)d_in[4];
    const float* Wv = (const float*)d_in[5];
    const float* bv = (const float*)d_in[6];
    float* out = (float*)d_out;

    cudaFuncSetAttribute((const void*)gemm_tc<0>, cudaFuncAttributeMaxDynamicSharedMemorySize, GEMM_SMEM);
    cudaFuncSetAttribute((const void*)gemm_tc<1>, cudaFuncAttributeMaxDynamicSharedMemorySize, GEMM_SMEM);
    cudaFuncSetAttribute((const void*)gemm_tc<2>, cudaFuncAttributeMaxDynamicSharedMemorySize, GEMM_SMEM);

    __half *xh, *pWq, *pWk, *pWv, *Qh, *Kh, *Vth, *Ph;
    float* Sp;
    cudaGetSymbolAddress((void**)&xh, g_xh);
    cudaGetSymbolAddress((void**)&pWq, g_Wq);  cudaGetSymbolAddress((void**)&pWk, g_Wk);
    cudaGetSymbolAddress((void**)&pWv, g_Wv);
    cudaGetSymbolAddress((void**)&Qh, g_Qh);   cudaGetSymbolAddress((void**)&Kh, g_Kh);
    cudaGetSymbolAddress((void**)&Vth, g_Vth);
    cudaGetSymbolAddress((void**)&Ph, g_Ph);
    cudaGetSymbolAddress((void**)&Sp, g_S);

    const float qscale = 0.03125f;   // 1/sqrt(1024), exact power of two

    // 1) fp16 operands
    convert_kernel<<<(size_t)BS * EMBED / 2048, 256>>>(x, xh, (size_t)BS * EMBED);
    convert_kernel<<<EMBED * EMBED / 2048, 256>>>(Wq, pWq, (size_t)EMBED * EMBED);
    convert_kernel<<<EMBED * EMBED / 2048, 256>>>(Wk, pWk, (size_t)EMBED * EMBED);
    convert_kernel<<<EMBED * EMBED / 2048, 256>>>(Wv, pWv, (size_t)EMBED * EMBED);

    // 2) Q = (x Wq^T + bq)*qscale -> Qh (z=0) ;  K = x Wk^T + bk -> Kh (z=1)
    {
        dim3 grid(EMBED / 256, BS / 128, 2);
        gemm_tc<1><<<grid, 256, GEMM_SMEM>>>(xh, pWq, bq, qscale,
                                             nullptr, Qh,
                                             EMBED, EMBED, EMBED, EMBED / 64, 0, 0, 0,
                                             pWk, bk, 1.0f, Kh);
    }
    // 3) Vt[e, bs] = Wv x^T + bv (row bias), ldc = BS
    {
        dim3 grid(BS / 256, EMBED / 128, 1);
        gemm_tc<2><<<grid, 256, GEMM_SMEM>>>(pWv, xh, bv, 1.0f,
                                             nullptr, Vth,
                                             EMBED, EMBED, BS, EMBED / 64, 0, 0, 0,
                                             nullptr, nullptr, 0.f, nullptr);
    }
    // 4) scores = Q K^T (scale folded into Q), batched, fp32 out
    {
        dim3 grid(SEQ / 256, SEQ / 128, BATCH);
        gemm_tc<0><<<grid, 256, GEMM_SMEM>>>(Qh, Kh, nullptr, 1.0f,
                                             Sp, nullptr,
                                             EMBED, EMBED, SEQ, EMBED / 64,
                                             (long long)SEQ * EMBED,
                                             (long long)SEQ * EMBED,
                                             (long long)SEQ * SEQ,
                                             nullptr, nullptr, 0.f, nullptr);
    }
    // 5) softmax -> fp16 P
    softmax_h<<<BATCH * SEQ, 256>>>(Sp, Ph);

    // 6) out = P V (B = Vt rows, per-batch column window), fp32 out
    {
        dim3 grid(EMBED / 256, SEQ / 128, BATCH);
        gemm_tc<0><<<grid, 256, GEMM_SMEM>>>(Ph, Vth, nullptr, 1.0f,
                                             out, nullptr,
                                             SEQ, BS, EMBED, SEQ / 64,
                                             (long long)SEQ * SEQ,
                                             (long long)SEQ,
                                             (long long)SEQ * EMBED,
                                             nullptr, nullptr, 0.f, nullptr);
    }
}

// round 10
// speedup vs baseline: 2.3551x; 1.0179x over previous
#include <cuda_runtime.h>
#include <cuda_fp16.h>
#include <cstdint>
#include <math.h>

#define BATCH 8
#define SEQ   2048
#define EMBED 1024
#define BS    (BATCH * SEQ)          // 16384

// ---------------------------------------------------------------------------
// Device-global scratch (allocation-free rule) — all fp16 operands
// ---------------------------------------------------------------------------
__device__ __half g_xh[(size_t)BS * EMBED];
__device__ __half g_Wq[EMBED * EMBED];
__device__ __half g_Wk[EMBED * EMBED];
__device__ __half g_Wv[EMBED * EMBED];
__device__ __half g_Qh[(size_t)BS * EMBED];
__device__ __half g_Kh[(size_t)BS * EMBED];
__device__ __half g_Vth[(size_t)EMBED * BS];   // V pre-transposed [EMBED][BS]
__device__ __half g_SP[(size_t)BATCH * SEQ * SEQ];  // scores, then softmax(P) in place

// ---------------------------------------------------------------------------
// Helpers
// ---------------------------------------------------------------------------
__device__ __forceinline__ uint32_t smem_u32(const void* p) {
    uint32_t a;
    asm("{ .reg .u64 t; cvta.to.shared.u64 t, %1; cvt.u32.u64 %0, t; }" : "=r"(a) : "l"(p));
    return a;
}

#define CP_ASYNC16(sm, gp) \
    asm volatile("cp.async.cg.shared.global [%0], [%1], 16;" :: "r"(sm), "l"(gp) : "memory")
#define CP_COMMIT()  asm volatile("cp.async.commit_group;" ::: "memory")
#define CP_WAITN(n)  asm volatile("cp.async.wait_group %0;" :: "n"(n) : "memory")

__device__ __forceinline__ void ldsm_x4(uint32_t* r, uint32_t addr) {
    asm volatile("ldmatrix.sync.aligned.m8n8.x4.shared.b16 {%0,%1,%2,%3}, [%4];"
                 : "=r"(r[0]), "=r"(r[1]), "=r"(r[2]), "=r"(r[3]) : "r"(addr));
}

__device__ __forceinline__ void mma16816(float* c, const uint32_t* a, const uint32_t* b) {
    asm volatile(
        "mma.sync.aligned.m16n8k16.row.col.f32.f16.f16.f32 "
        "{%0,%1,%2,%3}, {%4,%5,%6,%7}, {%8,%9}, {%0,%1,%2,%3};"
        : "+f"(c[0]), "+f"(c[1]), "+f"(c[2]), "+f"(c[3])
        : "r"(a[0]), "r"(a[1]), "r"(a[2]), "r"(a[3]), "r"(b[0]), "r"(b[1]));
}

// byte offset of 16B chunk (row, c) inside a [rows][64 fp16] tile, xor-swizzled
__device__ __forceinline__ uint32_t swz(int row, int c) {
    return (uint32_t)((row * 8 + (c ^ (row & 7))) * 16);
}

__device__ __forceinline__ uint32_t pack_half2(float v0, float v1) {
    __half h0 = __float2half(v0), h1 = __float2half(v1);
    return (uint32_t)__half_as_ushort(h0) | ((uint32_t)__half_as_ushort(h1) << 16);
}

// ---------------------------------------------------------------------------
// HMMA GEMM NT: C[M,N] = A[M,K] * B[N,K]^T, fp16 in, fp32 accum.
// CTA tile 128xNT (NT = 256 or 128), warp tile 64x(NT/4), 8 warps (2x4),
// K-chunk 64, 4-stage cp.async pipeline.
// MODE 0: C -> fp32 Cf (z-strided)
// MODE 1: v=(acc+bias[col])*scale -> fp16 Ch; blockIdx.z picks operand set
// MODE 2: v=acc+bias[row] -> fp16 Ch
// MODE 3: v=acc -> fp16 Ch (z-strided)   [score store]
// ---------------------------------------------------------------------------
#define NSTAGE 4

template <int MODE, int NT>
__global__ void __launch_bounds__(256, 1)
gemm_tc(const __half* __restrict__ Ah,
        const __half* B, const float* bias, float scale,
        float* __restrict__ Cf, __half* Ch,
        int lda, int ldb, int ldc, int nchunk,
        long long strideA, long long strideB, long long strideC,
        const __half* B2, const float* bias2, float scale2, __half* Ch2)
{
    constexpr int NG  = NT / 64;           // B ldsm groups per warp
    constexpr int NTL = NT / 32;           // 8-col mma subtiles per warp
    constexpr int STG_BYTES = 16384 + NT * 128;   // A 16KB + B NT*128B
    constexpr int B_OFF = 16384;

    extern __shared__ char smem[];
    const uint32_t sbase = smem_u32(smem);
    const int tid = threadIdx.x;
    const int wid = tid >> 5;
    const int lane = tid & 31;
    const int wm = wid & 1;          // 0..1  M direction (64 rows each)
    const int wn = wid >> 1;         // 0..3  N direction (NT/4 cols each)

    const long long z = blockIdx.z;
    if (MODE == 1) {
        if (z == 1) { B = B2; bias = bias2; scale = scale2; Ch = Ch2; }
    } else {
        Ah += z * strideA;
        B  += z * strideB;
    }

    const int rowA0 = blockIdx.y * 128;
    const int colB0 = blockIdx.x * NT;

    float acc[4][NTL][4];
#pragma unroll
    for (int mt = 0; mt < 4; mt++)
#pragma unroll
        for (int nt = 0; nt < NTL; nt++)
#pragma unroll
            for (int r = 0; r < 4; r++) acc[mt][nt][r] = 0.f;

    const __half* gA = Ah + (size_t)rowA0 * lda;
    const __half* gB = B  + (size_t)colB0 * ldb;

    // one stage: A 128x64 fp16 (16KB, 1024 chunks), B NTx64 fp16 (NT*8 chunks)
    auto issue_stage = [&](int kc, int stg) {
        const uint32_t sb = sbase + stg * STG_BYTES;
        const int k0 = kc * 64;
#pragma unroll
        for (int it = 0; it < 4; it++) {
            int idx = it * 256 + tid;
            int r = idx >> 3, c = idx & 7;
            uint32_t so = swz(r, c);
            CP_ASYNC16(sb + so, gA + (size_t)r * lda + k0 + c * 8);
        }
#pragma unroll
        for (int it = 0; it < NT / 32; it++) {
            int idx = it * 256 + tid;
            int r = idx >> 3, c = idx & 7;
            uint32_t so = swz(r, c);
            CP_ASYNC16(sb + B_OFF + so, gB + (size_t)r * ldb + k0 + c * 8);
        }
    };

    issue_stage(0, 0); CP_COMMIT();
    if (nchunk > 1) { issue_stage(1, 1); CP_COMMIT(); }
    if (nchunk > 2) { issue_stage(2, 2); CP_COMMIT(); }

    const int a_row = lane & 15;
    const int a_csel = lane >> 4;
    const int b_row = (lane & 7) + ((lane >> 4) << 3);
    const int b_csel = (lane >> 3) & 1;

    for (int kc = 0; kc < nchunk; kc++) {
        const int stg = kc & 3;
        const int ahead = nchunk - 1 - kc;
        if (kc + 3 < nchunk) {
            issue_stage(kc + 3, (kc + 3) & 3);
            CP_COMMIT();
            CP_WAITN(3);
        } else if (ahead == 2) {
            CP_WAITN(2);
        } else if (ahead == 1) {
            CP_WAITN(1);
        } else {
            CP_WAITN(0);
        }
        __syncthreads();

        const uint32_t sb = sbase + stg * STG_BYTES;
        const uint32_t aA = sb, bB = sb + B_OFF;

#pragma unroll
        for (int ks = 0; ks < 4; ks++) {
            uint32_t fA[4][4], fB[NG][4];
            const int kchunk = ks * 2;

#pragma unroll
            for (int mt = 0; mt < 4; mt++)
                ldsm_x4(fA[mt], aA + swz(wm * 64 + mt * 16 + a_row, kchunk + a_csel));
#pragma unroll
            for (int g = 0; g < NG; g++)
                ldsm_x4(fB[g], bB + swz(wn * (NT / 4) + g * 16 + b_row, kchunk + b_csel));

#pragma unroll
            for (int mt = 0; mt < 4; mt++)
#pragma unroll
                for (int nt = 0; nt < NTL; nt++)
                    mma16816(acc[mt][nt], fA[mt], &fB[nt >> 1][(nt & 1) * 2]);
        }
        __syncthreads();
    }

    // ------------------------------ epilogue ------------------------------
    const int lrow = (lane >> 2);
    const int lcol = (lane & 3) * 2;

#pragma unroll
    for (int mt = 0; mt < 4; mt++) {
#pragma unroll
        for (int half = 0; half < 2; half++) {
            const int row = rowA0 + wm * 64 + mt * 16 + lrow + half * 8;
            float rb = (MODE == 2) ? bias[row] : 0.f;
#pragma unroll
            for (int nt = 0; nt < NTL; nt++) {
                const int col = colB0 + wn * (NT / 4) + nt * 8 + lcol;
                float v0 = acc[mt][nt][half * 2 + 0];
                float v1 = acc[mt][nt][half * 2 + 1];
                if (MODE == 0) {
                    float2 o = make_float2(v0, v1);
                    *(float2*)(Cf + z * strideC + (size_t)row * ldc + col) = o;
                } else if (MODE == 3) {
                    *(uint32_t*)(Ch + z * strideC + (size_t)row * ldc + col) =
                        pack_half2(v0, v1);
                } else {
                    if (MODE == 1) { v0 = (v0 + bias[col]) * scale; v1 = (v1 + bias[col + 1]) * scale; }
                    else           { v0 = v0 + rb;                 v1 = v1 + rb; }
                    *(uint32_t*)(Ch + (size_t)row * ldc + col) = pack_half2(v0, v1);
                }
            }
        }
    }
}

// ---------------------------------------------------------------------------
// fp32 -> fp16 round: x (grid.y==0 path) and merged 3-weight variant
// ---------------------------------------------------------------------------
__global__ void __launch_bounds__(256, 8)
convert_kernel(const float* __restrict__ in, __half* __restrict__ out, size_t n)
{
    size_t i = ((size_t)blockIdx.x * blockDim.x + threadIdx.x) * 8;
    if (i >= n) return;
    float4 a = *(const float4*)(in + i);
    float4 b = *(const float4*)(in + i + 4);
    float v[8] = {a.x, a.y, a.z, a.w, b.x, b.y, b.z, b.w};
    alignas(16) uint32_t hw[4];
#pragma unroll
    for (int c = 0; c < 8; c += 2) hw[c >> 1] = pack_half2(v[c], v[c + 1]);
    *(uint4*)(out + i) = *(const uint4*)(&hw[0]);
}

__global__ void __launch_bounds__(256, 8)
convert3_kernel(const float* __restrict__ a, const float* __restrict__ b,
                const float* __restrict__ c,
                __half* __restrict__ oa, __half* __restrict__ ob,
                __half* __restrict__ oc, size_t n)
{
    const float* in;
    __half* out;
    if (blockIdx.y == 0)      { in = a; out = oa; }
    else if (blockIdx.y == 1) { in = b; out = ob; }
    else                      { in = c; out = oc; }
    size_t i = ((size_t)blockIdx.x * blockDim.x + threadIdx.x) * 8;
    if (i >= n) return;
    float4 p = *(const float4*)(in + i);
    float4 q = *(const float4*)(in + i + 4);
    float v[8] = {p.x, p.y, p.z, p.w, q.x, q.y, q.z, q.w};
    alignas(16) uint32_t hw[4];
#pragma unroll
    for (int cc = 0; cc < 8; cc += 2) hw[cc >> 1] = pack_half2(v[cc], v[cc + 1]);
    *(uint4*)(out + i) = *(const uint4*)(&hw[0]);
}

// ---------------------------------------------------------------------------
// Row softmax, fp16 in -> fp16 out, IN PLACE. One block per SEQ row.
// ---------------------------------------------------------------------------
__global__ void __launch_bounds__(256, 4)
softmax_h(__half* __restrict__ SP)
{
    __half* row = SP + (size_t)blockIdx.x * SEQ;
    const int t = threadIdx.x;

    uint4 raw = *(const uint4*)(row + t * 8);
    const uint32_t* w = (const uint32_t*)&raw;
    float v[8];
#pragma unroll
    for (int c = 0; c < 4; c++) {
        __half2 h2 = *(const __half2*)(&w[c]);
        float2 f2 = __half22float2(h2);
        v[c * 2 + 0] = f2.x;
        v[c * 2 + 1] = f2.y;
    }

    float mx = v[0];
#pragma unroll
    for (int i = 1; i < 8; i++) mx = fmaxf(mx, v[i]);

    __shared__ float red[256];
    red[t] = mx;
    __syncthreads();
#pragma unroll
    for (int s = 128; s > 0; s >>= 1) {
        if (t < s) red[t] = fmaxf(red[t], red[t + s]);
        __syncthreads();
    }
    mx = red[0];
    __syncthreads();

    float sum = 0.f;
#pragma unroll
    for (int i = 0; i < 8; i++) {
        v[i] = __expf(v[i] - mx);
        sum += v[i];
    }
    red[t] = sum;
    __syncthreads();
#pragma unroll
    for (int s = 128; s > 0; s >>= 1) {
        if (t < s) red[t] += red[t + s];
        __syncthreads();
    }
    const float inv = 1.f / red[0];

    alignas(16) uint32_t hw[4];
#pragma unroll
    for (int c = 0; c < 8; c += 2)
        hw[c >> 1] = pack_half2(v[c] * inv, v[c + 1] * inv);
    *(uint4*)(row + t * 8) = *(const uint4*)(&hw[0]);
}

// ---------------------------------------------------------------------------
// Launch
// ---------------------------------------------------------------------------
#define SMEM_256 (NSTAGE * (16384 + 256 * 128))   // 196608
#define SMEM_128 (NSTAGE * (16384 + 128 * 128))   // 131072

extern "C" void kernel_launch(void* const* d_in, const int* in_sizes, int n_in,
                              void* d_out, int out_size)
{
    const float* x  = (const float*)d_in[0];
    const float* Wq = (const float*)d_in[1];
    const float* bq = (const float*)d_in[2];
    const float* Wk = (const float*)d_in[3];
    const float* bk = (const float*)d_in[4];
    const float* Wv = (const float*)d_in[5];
    const float* bv = (const float*)d_in[6];
    float* out = (float*)d_out;

    cudaFuncSetAttribute((const void*)gemm_tc<1, 256>, cudaFuncAttributeMaxDynamicSharedMemorySize, SMEM_256);
    cudaFuncSetAttribute((const void*)gemm_tc<3, 256>, cudaFuncAttributeMaxDynamicSharedMemorySize, SMEM_256);
    cudaFuncSetAttribute((const void*)gemm_tc<2, 128>, cudaFuncAttributeMaxDynamicSharedMemorySize, SMEM_128);
    cudaFuncSetAttribute((const void*)gemm_tc<0, 128>, cudaFuncAttributeMaxDynamicSharedMemorySize, SMEM_128);

    __half *xh, *pWq, *pWk, *pWv, *Qh, *Kh, *Vth, *SP;
    cudaGetSymbolAddress((void**)&xh, g_xh);
    cudaGetSymbolAddress((void**)&pWq, g_Wq);  cudaGetSymbolAddress((void**)&pWk, g_Wk);
    cudaGetSymbolAddress((void**)&pWv, g_Wv);
    cudaGetSymbolAddress((void**)&Qh, g_Qh);   cudaGetSymbolAddress((void**)&Kh, g_Kh);
    cudaGetSymbolAddress((void**)&Vth, g_Vth);
    cudaGetSymbolAddress((void**)&SP, g_SP);

    const float qscale = 0.03125f;   // 1/sqrt(1024), exact power of two

    // 1) fp16 operands: x, and all three weights in one launch
    convert_kernel<<<(size_t)BS * EMBED / 2048, 256>>>(x, xh, (size_t)BS * EMBED);
    {
        dim3 grid(EMBED * EMBED / 2048, 3);
        convert3_kernel<<<grid, 256>>>(Wq, Wk, Wv, pWq, pWk, pWv, (size_t)EMBED * EMBED);
    }

    // 2) Q = (x Wq^T + bq)*qscale -> Qh (z=0) ;  K = x Wk^T + bk -> Kh (z=1)
    {
        dim3 grid(EMBED / 256, BS / 128, 2);   // 1024 CTAs
        gemm_tc<1, 256><<<grid, 256, SMEM_256>>>(xh, pWq, bq, qscale,
                                                 nullptr, Qh,
                                                 EMBED, EMBED, EMBED, EMBED / 64, 0, 0, 0,
                                                 pWk, bk, 1.0f, Kh);
    }
    // 3) Vt[e, bs] = Wv x^T + bv (row bias), NT=128, ldc = BS  (1024 CTAs)
    {
        dim3 grid(BS / 128, EMBED / 128, 1);
        gemm_tc<2, 128><<<grid, 256, SMEM_128>>>(pWv, xh, bv, 1.0f,
                                                 nullptr, Vth,
                                                 EMBED, EMBED, BS, EMBED / 64, 0, 0, 0,
                                                 nullptr, nullptr, 0.f, nullptr);
    }
    // 4) scores = Q K^T (scale folded into Q) -> fp16 SP, batched  (1024 CTAs)
    {
        dim3 grid(SEQ / 256, SEQ / 128, BATCH);
        gemm_tc<3, 256><<<grid, 256, SMEM_256>>>(Qh, Kh, nullptr, 1.0f,
                                                 nullptr, SP,
                                                 EMBED, EMBED, SEQ, EMBED / 64,
                                                 (long long)SEQ * EMBED,
                                                 (long long)SEQ * EMBED,
                                                 (long long)SEQ * SEQ,
                                                 nullptr, nullptr, 0.f, nullptr);
    }
    // 5) softmax in place on SP (fp16)
    softmax_h<<<BATCH * SEQ, 256>>>(SP);

    // 6) out = P V (B = Vt rows, per-batch column window), NT=128  (1024 CTAs)
    {
        dim3 grid(EMBED / 128, SEQ / 128, BATCH);
        gemm_tc<0, 128><<<grid, 256, SMEM_128>>>(SP, Vth, nullptr, 1.0f,
                                                 out, nullptr,
                                                 SEQ, BS, EMBED, SEQ / 64,
                                                 (long long)SEQ * SEQ,
                                                 (long long)SEQ,
                                                 (long long)SEQ * EMBED,
                                                 nullptr, nullptr, 0.f, nullptr);
    }
}